// round 3
// baseline (speedup 1.0000x reference)
#include <cuda_runtime.h>
#include <cuda_bf16.h>
#include <math.h>

// Problem constants
#define BB 16
#define CC 8
#define HH 512
#define WW 512
#define HWSZ (HH * WW)          // 262144
#define TXN 32                  // threads in x (one warp per row)
#define TYN 8                   // pixel rows per block
#define PX 4                    // pixels per thread (float4)
#define TW (TXN * PX)           // 128 tile width
#define NT (TXN * TYN)          // 256 threads
#define SROW 132                // 128 center + halo@128,129 + pad (16B-aligned rows)

#define N_FULL (16.0 * 8.0 * 512.0 * 512.0)   // 33554432
#define N_PIX  (16.0 * 512.0 * 512.0)         // 4194304
#define NCOLS  (BB * WW)                       // 8192

// Global accumulators. Zero-initialized at module load; bicon_final_kernel
// re-zeroes them after each use, so every kernel_launch sees zeros.
__device__ double g_acc[4];             // 0=conmap, 1=bimap, 2=bce, 3=decouple
__device__ float  g_isum[NCOLS];
__device__ float  g_jsum[NCOLS];
__device__ float  g_inter[NCOLS];

__device__ __forceinline__ float fsigmoid(float x) {
    return __fdividef(1.0f, 1.0f + __expf(-x));
}

__global__ __launch_bounds__(NT, 2)
void bicon_main_kernel(const float* __restrict__ cmap,
                       const int* __restrict__ target,
                       const int* __restrict__ con) {
    __shared__ __align__(16) float ps[CC][TYN + 2][SROW];  // sigmoid tile + halo
    __shared__ float dcol[3][TW];                          // dice column partials
    __shared__ float wred[NT / 32][4];

    const int tx = threadIdx.x, ty = threadIdx.y;
    const int tid = ty * TXN + tx;
    const int w0 = blockIdx.x * TW;
    const int h0 = blockIdx.y * TYN;
    const int b  = blockIdx.z;

    for (int i = tid; i < 3 * TW; i += NT) ((float*)dcol)[i] = 0.f;

    // ---- cooperative vectorized load + sigmoid of tile + halo ----
    {
        const float* basep = cmap + (long)b * CC * HWSZ;
        const int NCHUNK = CC * (TYN + 2);       // 80 (channel,row) chunks
        for (int o = tid; o < NCHUNK * 34; o += NT) {
            int chunk = o / 34, j = o - chunk * 34;
            int c  = chunk / (TYN + 2);
            int sy = chunk - c * (TYN + 2);
            int h  = h0 + sy - 1;
            const float* rowp = basep + (size_t)c * HWSZ + (size_t)h * WW;
            if (j < 32) {
                float4 s = make_float4(0.f, 0.f, 0.f, 0.f);
                if ((unsigned)h < HH) {
                    float4 v = *(const float4*)(rowp + w0 + 4 * j);
                    s.x = fsigmoid(v.x); s.y = fsigmoid(v.y);
                    s.z = fsigmoid(v.z); s.w = fsigmoid(v.w);
                }
                *(float4*)&ps[c][sy][4 * j] = s;
            } else {
                int w = (j == 32) ? (w0 - 1) : (w0 + TW);
                float sv = 0.f;
                if ((unsigned)h < HH && (unsigned)w < WW) sv = fsigmoid(rowp[w]);
                ps[c][sy][(j == 32) ? 128 : 129] = sv;
            }
        }
    }
    __syncthreads();

    const int h = h0 + ty;
    const unsigned FULL = 0xffffffffu;

    // centers
    float pc[CC][PX];
    #pragma unroll
    for (int c = 0; c < CC; c++) {
        float4 v = *(const float4*)&ps[c][ty + 1][4 * tx];
        pc[c][0] = v.x; pc[c][1] = v.y; pc[c][2] = v.z; pc[c][3] = v.w;
    }

    // DIRS = [(1,1),(0,1),(-1,1),(1,0),(-1,0),(1,-1),(0,-1),(-1,-1)]
    const int dxs[8] = {1, 0, -1, 1, -1, 1, 0, -1};
    const int dys[8] = {1, 1, 1, 0, 0, -1, -1, -1};

    // votes: vote[i](h,w) = p[i](h,w) * p[7-i](h-dy, w-dx); zero-padded shifts
    float vt[CC][PX];
    #pragma unroll
    for (int i = 0; i < CC; i++) {
        const float* rw = &ps[7 - i][ty + 1 - dys[i]][0];
        float4 v = *(const float4*)(rw + 4 * tx);
        float sh[PX];
        if (dxs[i] == 1) {            // value at w-1
            float u = __shfl_up_sync(FULL, v.w, 1);
            if (tx == 0) u = rw[128];
            sh[0] = u;   sh[1] = v.x; sh[2] = v.y; sh[3] = v.z;
        } else if (dxs[i] == -1) {    // value at w+1
            float d = __shfl_down_sync(FULL, v.x, 1);
            if (tx == 31) d = rw[129];
            sh[0] = v.y; sh[1] = v.z; sh[2] = v.w; sh[3] = d;
        } else {
            sh[0] = v.x; sh[1] = v.y; sh[2] = v.z; sh[3] = v.w;
        }
        #pragma unroll
        for (int j = 0; j < PX; j++) vt[i][j] = pc[i][j] * sh[j];
    }

    float fp[PX], pm[PX];
    #pragma unroll
    for (int j = 0; j < PX; j++) { fp[j] = vt[0][j]; pm[j] = vt[0][j]; }
    #pragma unroll
    for (int i = 1; i < CC; i++)
        #pragma unroll
        for (int j = 0; j < PX; j++) {
            fp[j] = fmaxf(fp[j], vt[i][j]);
            pm[j] = fminf(pm[j], vt[i][j]);
        }

    // con_target losses: log-of-products (4-factor groups), exact -100 clamp
    // semantics via explicit zero-factor bonus (only fires at image borders).
    float prod_p0[PX], prod_p1[PX], prod_v0[PX], prod_v1[PX], bonus[PX];
    int scn[PX];
    #pragma unroll
    for (int j = 0; j < PX; j++) {
        prod_p0[j] = prod_p1[j] = prod_v0[j] = prod_v1[j] = 1.f;
        bonus[j] = 0.f; scn[j] = 0;
    }
    #pragma unroll
    for (int c = 0; c < CC; c++) {
        int4 t4 = *(const int4*)(con + ((long)b * CC + c) * HWSZ
                                 + (size_t)h * WW + w0 + 4 * tx);
        int tv[PX] = {t4.x, t4.y, t4.z, t4.w};
        #pragma unroll
        for (int j = 0; j < PX; j++) {
            scn[j] += tv[j];
            float lp = tv[j] ? pc[c][j] : 1.f - pc[c][j];
            float lv = tv[j] ? vt[c][j] : 1.f - vt[c][j];
            bonus[j] += (lv == 0.f) ? 100.f : 0.f;
            lv = (lv == 0.f) ? 1.f : lv;
            if (c < 4) { prod_p0[j] *= lp; prod_v0[j] *= lv; }
            else       { prod_p1[j] *= lp; prod_v1[j] *= lv; }
        }
    }

    int4 tg4 = *(const int4*)(target + (long)b * HWSZ + (size_t)h * WW + w0 + 4 * tx);
    int tgv[PX] = {tg4.x, tg4.y, tg4.z, tg4.w};

    float conmap_part = 0.f, bimap_part = 0.f, bce_part = 0.f, dec_part = 0.f;
    #pragma unroll
    for (int j = 0; j < PX; j++) {
        conmap_part += -__logf(prod_p0[j]) - __logf(prod_p1[j]);
        bimap_part  += bonus[j] - __logf(prod_v0[j]) - __logf(prod_v1[j]);
        float bp = tgv[j] ? fp[j] : 1.f - fp[j];
        bce_part += fminf(-__logf(bp), 100.f);
        float edge = (scn[j] > 0 && scn[j] < 8) ? 1.f : 0.f;
        dec_part += fminf(-__logf(1.f - pm[j] * edge), 100.f);
        // dice column partials
        atomicAdd(&dcol[0][4 * tx + j], (float)tgv[j]);
        atomicAdd(&dcol[1][4 * tx + j], fp[j]);
        atomicAdd(&dcol[2][4 * tx + j], tgv[j] ? fp[j] : 0.f);
    }

    // ---- scalar reductions (warp shuffle -> shared -> global double) ----
    float v0 = conmap_part, v1 = bimap_part, v2 = bce_part, v3 = dec_part;
    #pragma unroll
    for (int o = 16; o > 0; o >>= 1) {
        v0 += __shfl_down_sync(FULL, v0, o);
        v1 += __shfl_down_sync(FULL, v1, o);
        v2 += __shfl_down_sync(FULL, v2, o);
        v3 += __shfl_down_sync(FULL, v3, o);
    }
    const int wid = tid >> 5, lane = tid & 31;
    if (lane == 0) {
        wred[wid][0] = v0; wred[wid][1] = v1; wred[wid][2] = v2; wred[wid][3] = v3;
    }
    __syncthreads();

    for (int i = tid; i < 3 * TW; i += NT) {
        int q = i / TW, cx = i - q * TW;
        float* dst = (q == 0) ? g_isum : (q == 1) ? g_jsum : g_inter;
        atomicAdd(&dst[b * WW + w0 + cx], dcol[q][cx]);
    }
    if (tid < 4) {
        float s = 0.f;
        #pragma unroll
        for (int j = 0; j < NT / 32; j++) s += wred[j][tid];
        atomicAdd(&g_acc[tid], (double)s);
    }
}

__global__ void bicon_final_kernel(float* __restrict__ out, int out_size) {
    __shared__ float red[256];
    __shared__ float loss_sh;
    const int tid = threadIdx.x;

    float s = 0.f;
    for (int i = tid; i < NCOLS; i += 256) {
        float ii = g_isum[i], jj = g_jsum[i], it = g_inter[i];
        s += 1.f - (2.f * it + 0.001f) / (ii + jj + 0.001f);
    }
    red[tid] = s;
    __syncthreads();
    for (int o = 128; o > 0; o >>= 1) {
        if (tid < o) red[tid] += red[tid + o];
        __syncthreads();
    }
    if (tid == 0) {
        double conmap_l = g_acc[0] / N_FULL;
        double bimap_l  = g_acc[1] / N_FULL;
        double bce_l    = g_acc[2] / N_PIX;
        double dec_l    = g_acc[3] / N_PIX;
        double dice_l   = (double)red[0] / (double)NCOLS;
        loss_sh = (float)(0.8 * conmap_l + dec_l + 0.2 * bimap_l + bce_l + dice_l);
    }
    __syncthreads();
    // re-zero accumulators for the next invocation (all reads are done)
    for (int i = tid; i < NCOLS; i += 256) {
        g_isum[i] = 0.f; g_jsum[i] = 0.f; g_inter[i] = 0.f;
    }
    if (tid < 4) g_acc[tid] = 0.0;
    for (int i = tid; i < out_size; i += 256) out[i] = loss_sh;
}

extern "C" void kernel_launch(void* const* d_in, const int* in_sizes, int n_in,
                              void* d_out, int out_size) {
    const float* cmap  = (const float*)d_in[0];   // [16,8,512,512] f32
    const int*   tgt   = (const int*)d_in[1];     // [16,1,512,512] i32
    const int*   con   = (const int*)d_in[2];     // [16,8,512,512] i32
    float* out = (float*)d_out;

    dim3 block(TXN, TYN);
    dim3 grid(WW / TW, HH / TYN, BB);   // 4 x 64 x 16 = 4096 blocks
    bicon_main_kernel<<<grid, block>>>(cmap, tgt, con);

    bicon_final_kernel<<<1, 256>>>(out, out_size);
}

// round 4
// speedup vs baseline: 2.0941x; 2.0941x over previous
#include <cuda_runtime.h>
#include <cuda_bf16.h>
#include <math.h>

// Problem constants
#define BB 16
#define CC 8
#define HH 512
#define WW 512
#define HWSZ (HH * WW)          // 262144
#define TXN 32                  // threads in x (one warp per row)
#define TYN 8                   // pixel rows per block
#define PX 4                    // pixels per thread (float4)
#define TW (TXN * PX)           // 128 tile width
#define NT (TXN * TYN)          // 256 threads
#define SROW 132                // 128 center + halo@128,129 + pad (16B aligned)
#define BCHUNK 4                // batches per main-kernel launch

#define N_FULL (16.0 * 8.0 * 512.0 * 512.0)   // 33554432
#define N_PIX  (16.0 * 512.0 * 512.0)         // 4194304
#define NCOLS  (BB * WW)                       // 8192

__device__ double g_acc[4];             // 0=conmap, 1=bimap, 2=bce, 3=decouple
__device__ float  g_isum[NCOLS];
__device__ float  g_jsum[NCOLS];
__device__ float  g_inter[NCOLS];

__global__ void bicon_zero_kernel() {
    int i = blockIdx.x * blockDim.x + threadIdx.x;
    if (i < NCOLS) { g_isum[i] = 0.f; g_jsum[i] = 0.f; g_inter[i] = 0.f; }
    if (i < 4) g_acc[i] = 0.0;
}

__device__ __forceinline__ float fsigmoid(float x) {
    return __fdividef(1.0f, 1.0f + __expf(-x));
}

__global__ __launch_bounds__(NT, 4)
void bicon_main_kernel(const float* __restrict__ cmap,
                       const int* __restrict__ target,
                       const int* __restrict__ con, int b0) {
    __shared__ __align__(16) float ps[CC][TYN + 2][SROW];  // 42.2 KB
    __shared__ float wred[NT / 32][4];

    const int tx = threadIdx.x, ty = threadIdx.y;
    const int tid = ty * TXN + tx;
    const int w0 = blockIdx.x * TW;
    const int h0 = blockIdx.y * TYN;
    const int b  = b0 + blockIdx.z;
    const unsigned FULL = 0xffffffffu;

    // ---- tile build: sigmoid of [8ch][10 rows][128 + 2 halo] ----
    {
        const float* basep = cmap + (long)b * CC * HWSZ;
        #pragma unroll 5
        for (int o = tid; o < CC * (TYN + 2) * 32; o += NT) {   // vector part
            int chunk = o >> 5, j = o & 31;
            int c  = chunk / (TYN + 2);
            int sy = chunk - c * (TYN + 2);
            int h  = h0 + sy - 1;
            float4 s = make_float4(0.f, 0.f, 0.f, 0.f);
            if ((unsigned)h < HH) {
                float4 v = *(const float4*)(basep + (size_t)c * HWSZ
                                            + (size_t)h * WW + w0 + 4 * j);
                s.x = fsigmoid(v.x); s.y = fsigmoid(v.y);
                s.z = fsigmoid(v.z); s.w = fsigmoid(v.w);
            }
            *(float4*)&ps[c][sy][4 * j] = s;
        }
        for (int o = tid; o < CC * (TYN + 2) * 2; o += NT) {    // halo scalars
            int chunk = o >> 1, side = o & 1;
            int c  = chunk / (TYN + 2);
            int sy = chunk - c * (TYN + 2);
            int h  = h0 + sy - 1;
            int w  = side ? (w0 + TW) : (w0 - 1);
            float sv = 0.f;
            if ((unsigned)h < HH && (unsigned)w < WW)
                sv = fsigmoid(basep[(size_t)c * HWSZ + (size_t)h * WW + w]);
            ps[c][sy][128 + side] = sv;
        }
    }
    __syncthreads();

    const int h = h0 + ty;

    // DIRS = [(1,1),(0,1),(-1,1),(1,0),(-1,0),(1,-1),(0,-1),(-1,-1)]
    const int dxs[8] = {1, 0, -1, 1, -1, 1, 0, -1};
    const int dys[8] = {1, 1, 1, 0, 0, -1, -1, -1};

    float fp[PX] = {0.f, 0.f, 0.f, 0.f};       // votes >= 0
    float pm[PX] = {1.f, 1.f, 1.f, 1.f};       // votes < 1
    float prod_p[PX]  = {1.f, 1.f, 1.f, 1.f};  // conmap: 8-factor product
    float prod_v0[PX] = {1.f, 1.f, 1.f, 1.f};  // bimap: two 4-factor products
    float prod_v1[PX] = {1.f, 1.f, 1.f, 1.f};
    float bonus[PX]   = {0.f, 0.f, 0.f, 0.f};
    int   scn[PX]     = {0, 0, 0, 0};

    const int* conp = con + (long)b * CC * HWSZ + (size_t)h * WW + w0 + 4 * tx;

    #pragma unroll
    for (int c = 0; c < CC; c++) {
        // center p[c]
        float4 pc4 = *(const float4*)&ps[c][ty + 1][4 * tx];
        float pcv[PX] = {pc4.x, pc4.y, pc4.z, pc4.w};
        // shifted p[7-c] in direction DIRS[c]
        const float* rw = &ps[7 - c][ty + 1 - dys[c]][0];
        float4 v = *(const float4*)(rw + 4 * tx);
        float sh[PX];
        if (dxs[c] == 1) {
            float u = __shfl_up_sync(FULL, v.w, 1);
            if (tx == 0) u = rw[128];
            sh[0] = u;   sh[1] = v.x; sh[2] = v.y; sh[3] = v.z;
        } else if (dxs[c] == -1) {
            float d = __shfl_down_sync(FULL, v.x, 1);
            if (tx == 31) d = rw[129];
            sh[0] = v.y; sh[1] = v.z; sh[2] = v.w; sh[3] = d;
        } else {
            sh[0] = v.x; sh[1] = v.y; sh[2] = v.z; sh[3] = v.w;
        }
        int4 t4 = *(const int4*)(conp + (size_t)c * HWSZ);
        int tv[PX] = {t4.x, t4.y, t4.z, t4.w};
        #pragma unroll
        for (int j = 0; j < PX; j++) {
            float vt = pcv[j] * sh[j];
            fp[j] = fmaxf(fp[j], vt);
            pm[j] = fminf(pm[j], vt);
            scn[j] += tv[j];
            float lp = tv[j] ? pcv[j] : 1.f - pcv[j];
            float lv = tv[j] ? vt     : 1.f - vt;
            bonus[j] += (lv == 0.f) ? 100.f : 0.f;
            lv = (lv == 0.f) ? 1.f : lv;
            prod_p[j] *= lp;
            if (c < 4) prod_v0[j] *= lv; else prod_v1[j] *= lv;
        }
    }

    int4 tg4 = *(const int4*)(target + (long)b * HWSZ + (size_t)h * WW + w0 + 4 * tx);
    int tgv[PX] = {tg4.x, tg4.y, tg4.z, tg4.w};

    // conmap/bimap per-pixel logs; bce & dec grouped across the 4 pixels
    // (their per-element -100 clamp is provably never active: fp>0, pm<1).
    float conmap_part = 0.f, bimap_part = 0.f;
    float bce_prod = 1.f, dec_prod = 1.f;
    #pragma unroll
    for (int j = 0; j < PX; j++) {
        conmap_part += -__logf(prod_p[j]);
        bimap_part  += bonus[j] - __logf(prod_v0[j]) - __logf(prod_v1[j]);
        bce_prod *= tgv[j] ? fp[j] : 1.f - fp[j];
        float edge = (scn[j] > 0 && scn[j] < 8) ? 1.f : 0.f;
        dec_prod *= 1.f - pm[j] * edge;
    }
    float bce_part = -__logf(bce_prod);
    float dec_part = -__logf(dec_prod);

    // ---- dice column staging: reuse ps memory (tile fully consumed) ----
    __syncthreads();
    float* dst = &ps[0][0][0];   // [3][TYN][TW] = 3072 floats << tile size
    #pragma unroll
    for (int j = 0; j < PX; j++) {
        dst[(0 * TYN + ty) * TW + 4 * tx + j] = (float)tgv[j];
        dst[(1 * TYN + ty) * TW + 4 * tx + j] = fp[j];
        dst[(2 * TYN + ty) * TW + 4 * tx + j] = tgv[j] ? fp[j] : 0.f;
    }

    // ---- scalar reductions ----
    float v0 = conmap_part, v1 = bimap_part, v2 = bce_part, v3 = dec_part;
    #pragma unroll
    for (int o = 16; o > 0; o >>= 1) {
        v0 += __shfl_down_sync(FULL, v0, o);
        v1 += __shfl_down_sync(FULL, v1, o);
        v2 += __shfl_down_sync(FULL, v2, o);
        v3 += __shfl_down_sync(FULL, v3, o);
    }
    const int wid = tid >> 5, lane = tid & 31;
    if (lane == 0) {
        wred[wid][0] = v0; wred[wid][1] = v1; wred[wid][2] = v2; wred[wid][3] = v3;
    }
    __syncthreads();

    for (int i = tid; i < 3 * TW; i += NT) {
        int q = i >> 7, col = i & (TW - 1);
        float s = 0.f;
        #pragma unroll
        for (int r = 0; r < TYN; r++) s += dst[(q * TYN + r) * TW + col];
        float* gp = (q == 0) ? g_isum : (q == 1) ? g_jsum : g_inter;
        atomicAdd(&gp[b * WW + w0 + col], s);
    }
    if (tid < 4) {
        float s = 0.f;
        #pragma unroll
        for (int j = 0; j < NT / 32; j++) s += wred[j][tid];
        atomicAdd(&g_acc[tid], (double)s);
    }
}

__global__ void bicon_final_kernel(float* __restrict__ out, int out_size) {
    __shared__ float red[1024];
    __shared__ float loss_sh;
    const int tid = threadIdx.x;

    float s = 0.f;
    #pragma unroll
    for (int k = 0; k < NCOLS / 1024; k++) {
        int i = tid + k * 1024;
        float ii = g_isum[i], jj = g_jsum[i], it = g_inter[i];
        s += 1.f - __fdividef(2.f * it + 0.001f, ii + jj + 0.001f);
    }
    red[tid] = s;
    __syncthreads();
    for (int o = 512; o > 0; o >>= 1) {
        if (tid < o) red[tid] += red[tid + o];
        __syncthreads();
    }
    if (tid == 0) {
        double conmap_l = g_acc[0] / N_FULL;
        double bimap_l  = g_acc[1] / N_FULL;
        double bce_l    = g_acc[2] / N_PIX;
        double dec_l    = g_acc[3] / N_PIX;
        double dice_l   = (double)red[0] / (double)NCOLS;
        loss_sh = (float)(0.8 * conmap_l + dec_l + 0.2 * bimap_l + bce_l + dice_l);
    }
    __syncthreads();
    for (int i = tid; i < out_size; i += 1024) out[i] = loss_sh;
}

extern "C" void kernel_launch(void* const* d_in, const int* in_sizes, int n_in,
                              void* d_out, int out_size) {
    const float* cmap  = (const float*)d_in[0];   // [16,8,512,512] f32
    const int*   tgt   = (const int*)d_in[1];     // [16,1,512,512] i32
    const int*   con   = (const int*)d_in[2];     // [16,8,512,512] i32
    float* out = (float*)d_out;

    bicon_zero_kernel<<<8, 1024>>>();

    dim3 block(TXN, TYN);
    dim3 grid(WW / TW, HH / TYN, BCHUNK);   // 4 x 64 x 4 = 1024 blocks/chunk
    for (int b0 = 0; b0 < BB; b0 += BCHUNK)
        bicon_main_kernel<<<grid, block>>>(cmap, tgt, con, b0);

    bicon_final_kernel<<<1, 1024>>>(out, out_size);
}

// round 5
// speedup vs baseline: 2.1843x; 1.0431x over previous
#include <cuda_runtime.h>
#include <cuda_bf16.h>
#include <math.h>

// Problem constants
#define BB 16
#define CC 8
#define HH 512
#define WW 512
#define HWSZ (HH * WW)          // 262144
#define TXN 32                  // threads in x (one warp per row)
#define TYN 8                   // pixel rows per block
#define PX 4                    // pixels per thread (float4)
#define TW (TXN * PX)           // 128 tile width
#define NT (TXN * TYN)          // 256 threads
#define SROW 132                // 128 center + halo@128,129 + pad (16B aligned)
#define BCHUNK 8                // batches per main-kernel launch

#define N_FULL (16.0 * 8.0 * 512.0 * 512.0)   // 33554432
#define N_PIX  (16.0 * 512.0 * 512.0)         // 4194304
#define NCOLS  (BB * WW)                       // 8192

__device__ double g_acc[4];             // 0=conmap, 1=bimap, 2=bce, 3=decouple
__device__ float  g_isum[NCOLS];
__device__ float  g_jsum[NCOLS];
__device__ float  g_inter[NCOLS];

__global__ void bicon_zero_kernel() {
    int i = blockIdx.x * blockDim.x + threadIdx.x;
    if (i < NCOLS) { g_isum[i] = 0.f; g_jsum[i] = 0.f; g_inter[i] = 0.f; }
    if (i < 4) g_acc[i] = 0.0;
}

__device__ __forceinline__ float fsigmoid(float x) {
    return __fdividef(1.0f, 1.0f + __expf(-x));
}

__global__ __launch_bounds__(NT, 5)
void bicon_main_kernel(const float* __restrict__ cmap,
                       const int* __restrict__ target,
                       const int* __restrict__ con, int b0) {
    __shared__ __align__(16) float ps[CC][TYN + 2][SROW];  // 42.2 KB
    __shared__ float wred[NT / 32][4];

    const int tx = threadIdx.x, ty = threadIdx.y;
    const int tid = ty * TXN + tx;
    const int w0 = blockIdx.x * TW;
    const int h0 = blockIdx.y * TYN;
    const int b  = b0 + blockIdx.z;
    const unsigned FULL = 0xffffffffu;

    // ---- tile build: sigmoid of [8ch][10 rows][128 + 2 halo] ----
    {
        const float* basep = cmap + (long)b * CC * HWSZ;
        #pragma unroll 5
        for (int o = tid; o < CC * (TYN + 2) * 32; o += NT) {   // vector part
            int chunk = o >> 5, j = o & 31;
            int c  = chunk / (TYN + 2);
            int sy = chunk - c * (TYN + 2);
            int h  = h0 + sy - 1;
            float4 s = make_float4(0.f, 0.f, 0.f, 0.f);
            if ((unsigned)h < HH) {
                float4 v = *(const float4*)(basep + (size_t)c * HWSZ
                                            + (size_t)h * WW + w0 + 4 * j);
                s.x = fsigmoid(v.x); s.y = fsigmoid(v.y);
                s.z = fsigmoid(v.z); s.w = fsigmoid(v.w);
            }
            *(float4*)&ps[c][sy][4 * j] = s;
        }
        for (int o = tid; o < CC * (TYN + 2) * 2; o += NT) {    // halo scalars
            int chunk = o >> 1, side = o & 1;
            int c  = chunk / (TYN + 2);
            int sy = chunk - c * (TYN + 2);
            int h  = h0 + sy - 1;
            int w  = side ? (w0 + TW) : (w0 - 1);
            float sv = 0.f;
            if ((unsigned)h < HH && (unsigned)w < WW)
                sv = fsigmoid(basep[(size_t)c * HWSZ + (size_t)h * WW + w]);
            ps[c][sy][128 + side] = sv;
        }
    }

    const int h = h0 + ty;

    // ---- front-batched global loads (MLP=9): con masks + target ----
    // con values are exactly 0/1 -> compress 8 channels into one byte/pixel.
    unsigned cm[PX] = {0u, 0u, 0u, 0u};
    {
        const int* conp = con + (long)b * CC * HWSZ + (size_t)h * WW + w0 + 4 * tx;
        #pragma unroll
        for (int c = 0; c < CC; c++) {
            int4 t4 = *(const int4*)(conp + (size_t)c * HWSZ);
            cm[0] |= ((unsigned)t4.x) << c;
            cm[1] |= ((unsigned)t4.y) << c;
            cm[2] |= ((unsigned)t4.z) << c;
            cm[3] |= ((unsigned)t4.w) << c;
        }
    }
    int4 tg4 = *(const int4*)(target + (long)b * HWSZ + (size_t)h * WW + w0 + 4 * tx);
    int tgv[PX] = {tg4.x, tg4.y, tg4.z, tg4.w};

    __syncthreads();

    // DIRS = [(1,1),(0,1),(-1,1),(1,0),(-1,0),(1,-1),(0,-1),(-1,-1)]
    const int dxs[8] = {1, 0, -1, 1, -1, 1, 0, -1};
    const int dys[8] = {1, 1, 1, 0, 0, -1, -1, -1};

    float fp[PX] = {0.f, 0.f, 0.f, 0.f};       // votes >= 0
    float pm[PX] = {1.f, 1.f, 1.f, 1.f};       // votes < 1
    float prod_p[PX]  = {1.f, 1.f, 1.f, 1.f};  // conmap: 8-factor product
    float prod_v0[PX] = {1.f, 1.f, 1.f, 1.f};  // bimap: two 4-factor products
    float prod_v1[PX] = {1.f, 1.f, 1.f, 1.f};
    float bonus[PX]   = {0.f, 0.f, 0.f, 0.f};

    #pragma unroll
    for (int c = 0; c < CC; c++) {
        // center p[c]
        float4 pc4 = *(const float4*)&ps[c][ty + 1][4 * tx];
        float pcv[PX] = {pc4.x, pc4.y, pc4.z, pc4.w};
        // shifted p[7-c] in direction DIRS[c]
        const float* rw = &ps[7 - c][ty + 1 - dys[c]][0];
        float4 v = *(const float4*)(rw + 4 * tx);
        float sh[PX];
        if (dxs[c] == 1) {
            float u = __shfl_up_sync(FULL, v.w, 1);
            if (tx == 0) u = rw[128];
            sh[0] = u;   sh[1] = v.x; sh[2] = v.y; sh[3] = v.z;
        } else if (dxs[c] == -1) {
            float d = __shfl_down_sync(FULL, v.x, 1);
            if (tx == 31) d = rw[129];
            sh[0] = v.y; sh[1] = v.z; sh[2] = v.w; sh[3] = d;
        } else {
            sh[0] = v.x; sh[1] = v.y; sh[2] = v.z; sh[3] = v.w;
        }
        #pragma unroll
        for (int j = 0; j < PX; j++) {
            float vt = pcv[j] * sh[j];
            fp[j] = fmaxf(fp[j], vt);
            pm[j] = fminf(pm[j], vt);
            bool t = (cm[j] >> c) & 1u;
            float lp = t ? pcv[j] : 1.f - pcv[j];
            float lv = t ? vt     : 1.f - vt;
            bonus[j] += (lv == 0.f) ? 100.f : 0.f;
            lv = (lv == 0.f) ? 1.f : lv;
            prod_p[j] *= lp;
            if (c < 4) prod_v0[j] *= lv; else prod_v1[j] *= lv;
        }
    }

    // conmap/bimap per-pixel logs; bce & dec grouped across the 4 pixels
    // (their per-element -100 clamp is provably never active: fp>0, pm<1).
    float conmap_part = 0.f, bimap_part = 0.f;
    float bce_prod = 1.f, dec_prod = 1.f;
    #pragma unroll
    for (int j = 0; j < PX; j++) {
        conmap_part += -__logf(prod_p[j]);
        bimap_part  += bonus[j] - __logf(prod_v0[j]) - __logf(prod_v1[j]);
        bce_prod *= tgv[j] ? fp[j] : 1.f - fp[j];
        int scn = __popc(cm[j]);
        float edge = (scn > 0 && scn < 8) ? 1.f : 0.f;
        dec_prod *= 1.f - pm[j] * edge;
    }
    float bce_part = -__logf(bce_prod);
    float dec_part = -__logf(dec_prod);

    // ---- dice column staging: reuse ps memory (tile fully consumed) ----
    __syncthreads();
    float* dst = &ps[0][0][0];   // [3][TYN][TW] = 3072 floats << tile size
    #pragma unroll
    for (int j = 0; j < PX; j++) {
        dst[(0 * TYN + ty) * TW + 4 * tx + j] = (float)tgv[j];
        dst[(1 * TYN + ty) * TW + 4 * tx + j] = fp[j];
        dst[(2 * TYN + ty) * TW + 4 * tx + j] = tgv[j] ? fp[j] : 0.f;
    }

    // ---- scalar reductions ----
    float v0 = conmap_part, v1 = bimap_part, v2 = bce_part, v3 = dec_part;
    #pragma unroll
    for (int o = 16; o > 0; o >>= 1) {
        v0 += __shfl_down_sync(FULL, v0, o);
        v1 += __shfl_down_sync(FULL, v1, o);
        v2 += __shfl_down_sync(FULL, v2, o);
        v3 += __shfl_down_sync(FULL, v3, o);
    }
    const int wid = tid >> 5, lane = tid & 31;
    if (lane == 0) {
        wred[wid][0] = v0; wred[wid][1] = v1; wred[wid][2] = v2; wred[wid][3] = v3;
    }
    __syncthreads();

    for (int i = tid; i < 3 * TW; i += NT) {
        int q = i >> 7, col = i & (TW - 1);
        float s = 0.f;
        #pragma unroll
        for (int r = 0; r < TYN; r++) s += dst[(q * TYN + r) * TW + col];
        float* gp = (q == 0) ? g_isum : (q == 1) ? g_jsum : g_inter;
        atomicAdd(&gp[b * WW + w0 + col], s);
    }
    if (tid < 4) {
        float s = 0.f;
        #pragma unroll
        for (int j = 0; j < NT / 32; j++) s += wred[j][tid];
        atomicAdd(&g_acc[tid], (double)s);
    }
}

__global__ void bicon_final_kernel(float* __restrict__ out, int out_size) {
    __shared__ float red[1024];
    __shared__ float loss_sh;
    const int tid = threadIdx.x;

    float s = 0.f;
    #pragma unroll
    for (int k = 0; k < NCOLS / 1024; k++) {
        int i = tid + k * 1024;
        float ii = g_isum[i], jj = g_jsum[i], it = g_inter[i];
        s += 1.f - __fdividef(2.f * it + 0.001f, ii + jj + 0.001f);
    }
    red[tid] = s;
    __syncthreads();
    for (int o = 512; o > 0; o >>= 1) {
        if (tid < o) red[tid] += red[tid + o];
        __syncthreads();
    }
    if (tid == 0) {
        double conmap_l = g_acc[0] / N_FULL;
        double bimap_l  = g_acc[1] / N_FULL;
        double bce_l    = g_acc[2] / N_PIX;
        double dec_l    = g_acc[3] / N_PIX;
        double dice_l   = (double)red[0] / (double)NCOLS;
        loss_sh = (float)(0.8 * conmap_l + dec_l + 0.2 * bimap_l + bce_l + dice_l);
    }
    __syncthreads();
    for (int i = tid; i < out_size; i += 1024) out[i] = loss_sh;
}

extern "C" void kernel_launch(void* const* d_in, const int* in_sizes, int n_in,
                              void* d_out, int out_size) {
    const float* cmap  = (const float*)d_in[0];   // [16,8,512,512] f32
    const int*   tgt   = (const int*)d_in[1];     // [16,1,512,512] i32
    const int*   con   = (const int*)d_in[2];     // [16,8,512,512] i32
    float* out = (float*)d_out;

    bicon_zero_kernel<<<8, 1024>>>();

    dim3 block(TXN, TYN);
    dim3 grid(WW / TW, HH / TYN, BCHUNK);   // 4 x 64 x 8 = 2048 blocks/chunk
    for (int b0 = 0; b0 < BB; b0 += BCHUNK)
        bicon_main_kernel<<<grid, block>>>(cmap, tgt, con, b0);

    bicon_final_kernel<<<1, 1024>>>(out, out_size);
}